// round 12
// baseline (speedup 1.0000x reference)
#include <cuda_runtime.h>
#include <cuda_fp16.h>
#include <cstdint>

// ---------------- problem constants ----------------
#define B_SZ   32768
#define DIN    512
#define DOUT   512
#define NLEV   10
#define NHB    64                  // scatter blocks (x512 thr)

// ---------------- GEMM tiling ----------------
#define BM     128
#define BN     128
#define BK     64                  // k per stage: A fp32 256B/row, B fp16 128B/row
#define NKB    (DIN / BK)          // 8 K-blocks
#define MAX_MT 266
#define NT     (DOUT / BN)         // 4 N-tiles
#define A_SZ   (BM * 256)          // 32768 B per stage (fp32)
#define B_SZ_S (BN * 128)          // 16384 B per stage (fp16)
#define STG_TOT (A_SZ + B_SZ_S)    // 49152 B
#define SMEM_BYTES (2 * STG_TOT)   // 98304

// ---------------- device scratch ----------------
__device__ int g_counts[NLEV];
__device__ int g_offsets[NLEV];
__device__ int g_rows[B_SZ];
// folded per-level matrices in fp16, [level][n][k]
__device__ __align__(16) __half g_M16[NLEV * DOUT * DIN];

// ---------------- PTX helpers ----------------
__device__ __forceinline__ uint32_t smem_u32(const void* p) {
    uint32_t a;
    asm("{ .reg .u64 t; cvta.to.shared.u64 t, %1; cvt.u32.u64 %0, t; }" : "=r"(a) : "l"(p));
    return a;
}
#define CP16(dst, src) \
    asm volatile("cp.async.cg.shared.global [%0], [%1], 16;" :: "r"(dst), "l"(src))
#define CP_COMMIT() asm volatile("cp.async.commit_group;" ::: "memory")
#define CP_WAIT0()  asm volatile("cp.async.wait_group 0;" ::: "memory")

#define LDSM4(r0, r1, r2, r3, addr) \
    asm volatile("ldmatrix.sync.aligned.m8n8.x4.shared.b16 {%0,%1,%2,%3}, [%4];" \
        : "=r"(r0), "=r"(r1), "=r"(r2), "=r"(r3) : "r"(addr))

__device__ __forceinline__ void mma16(float* d, const uint32_t* a, const uint32_t* b) {
    asm volatile(
        "mma.sync.aligned.m16n8k16.row.col.f32.f16.f16.f32 "
        "{%0,%1,%2,%3}, {%4,%5,%6,%7}, {%8,%9}, {%0,%1,%2,%3};"
        : "+f"(d[0]), "+f"(d[1]), "+f"(d[2]), "+f"(d[3])
        : "r"(a[0]), "r"(a[1]), "r"(a[2]), "r"(a[3]), "r"(b[0]), "r"(b[1]));
}

__device__ __forceinline__ uint32_t cvt2(float2 f) {
    __half2 h = __floats2half2_rn(f.x, f.y);
    return *reinterpret_cast<uint32_t*>(&h);
}

// B smem swizzle (128B rows, 8 x 16B units)
__device__ __forceinline__ uint32_t swzB(int row, int u) {
    return (uint32_t)row * 128u + (uint32_t)((u ^ (row & 7)) << 4);
}

// per-block int64-vs-int32 detection over first 2KB
__device__ __forceinline__ int detect_is64(const void* val, int tid) {
    int bad = 0;
    if (tid < 256) bad = (((const unsigned long long*)val)[tid] >= 10ULL);
    return __syncthreads_count(bad) == 0;
}
__device__ __forceinline__ int load_val(const void* val, int b, int is64) {
    int v = is64 ? (int)((const long long*)val)[b] : ((const int*)val)[b];
    return v < 0 ? 0 : (v > 9 ? 9 : v);
}

// =================================================================
// Kernel 1 (fully fused prep):
//   blocks 0..63    : full-histogram (register-packed) + cross-block
//                     prefix + scatter of this block's 512 rows
//   blocks 64..191  : fold M[v] = sum_l C[v,l] * W[l]  (fp16 out)
// =================================================================
__global__ void k_prep(const void* __restrict__ val, const float* __restrict__ W,
                       const float* __restrict__ gates, const float* __restrict__ attn) {
    int tid = threadIdx.x, bid = blockIdx.x;
    if (bid < NHB) {
        // ---------- scatter block ----------
        __shared__ int stot[NLEV];   // total counts (all 32768)
        __shared__ int spre[NLEV];   // counts among rows < bid*512
        __shared__ int sbase[NLEV], srank[NLEV];
        int is64 = detect_is64(val, tid);
        if (tid < NLEV) { stot[tid] = 0; spre[tid] = 0; srank[tid] = 0; }
        __syncthreads();

        // each thread counts 64 values (coalesced stride-512 walk),
        // packed into 2x u64 (5 fields x 12 bits), twice (total / prefix)
        unsigned long long at0 = 0, at1 = 0, ap0 = 0, ap1 = 0;
        int lim = bid * 512;
        for (int i = 0; i < 64; i++) {
            int idx = tid + (i << 9);
            int v = load_val(val, idx, is64);
            int hi = v >= 5;
            unsigned long long f = 1ULL << (12 * (v - 5 * hi));
            if (hi) at1 += f; else at0 += f;
            if (idx < lim) { if (hi) ap1 += f; else ap0 += f; }
        }
        // warp reduce (max field value 32*64 = 2048 < 4096)
#pragma unroll
        for (int o = 16; o; o >>= 1) {
            at0 += __shfl_xor_sync(0xFFFFFFFFu, at0, o);
            at1 += __shfl_xor_sync(0xFFFFFFFFu, at1, o);
            ap0 += __shfl_xor_sync(0xFFFFFFFFu, ap0, o);
            ap1 += __shfl_xor_sync(0xFFFFFFFFu, ap1, o);
        }
        if ((tid & 31) == 0) {
#pragma unroll
            for (int l = 0; l < 5; l++) {
                atomicAdd(&stot[l],     (int)((at0 >> (12 * l)) & 0xFFF));
                atomicAdd(&stot[l + 5], (int)((at1 >> (12 * l)) & 0xFFF));
                atomicAdd(&spre[l],     (int)((ap0 >> (12 * l)) & 0xFFF));
                atomicAdd(&spre[l + 5], (int)((ap1 >> (12 * l)) & 0xFFF));
            }
        }
        __syncthreads();
        if (tid == 0) {
            int a = 0;
            for (int l = 0; l < NLEV; l++) {
                sbase[l] = a + spre[l];
                if (bid == 0) { g_counts[l] = stot[l]; g_offsets[l] = a; }
                a += stot[l];
            }
        }
        __syncthreads();

        int b = bid * 512 + tid;
        int v = load_val(val, b, is64);
        int rank = atomicAdd(&srank[v], 1);
        g_rows[sbase[v] + rank] = b;
    } else {
        // ---------- fold block ----------
        __shared__ float sC[NLEV][NLEV];
        if (tid < NLEV) {
            int v = tid;
            float m = -1e30f;
            for (int l = 0; l < NLEV; l++) m = fmaxf(m, attn[v * NLEV + l]);
            float e[NLEV]; float ssum = 0.f;
            for (int l = 0; l < NLEV; l++) { e[l] = expf(attn[v * NLEV + l] - m); ssum += e[l]; }
            float inv = 1.f / ssum;
            float gv = 1.f / (1.f + expf(-gates[v]));
            for (int l = 0; l < NLEV; l++) {
                float gl = 1.f / (1.f + expf(-gates[l]));
                sC[v][l] = 0.3f * e[l] * inv * gl + ((l == v) ? 0.7f * gv : 0.f);
            }
        }
        __syncthreads();

        int p  = (bid - NHB) * 512 + tid;
        int n  = p >> 7;
        int k4 = p & 127;

        float4 w[NLEV];
#pragma unroll
        for (int l = 0; l < NLEV; l++)
            w[l] = __ldg((const float4*)(W + ((size_t)l * DOUT + n) * DIN) + k4);

#pragma unroll
        for (int v = 0; v < NLEV; v++) {
            float4 a = make_float4(0.f, 0.f, 0.f, 0.f);
#pragma unroll
            for (int l = 0; l < NLEV; l++) {
                float cc = sC[v][l];
                a.x += cc * w[l].x; a.y += cc * w[l].y;
                a.z += cc * w[l].z; a.w += cc * w[l].w;
            }
            __half2 h0 = __floats2half2_rn(a.x, a.y);
            __half2 h1 = __floats2half2_rn(a.z, a.w);
            uint2 o;
            o.x = *reinterpret_cast<unsigned*>(&h0);
            o.y = *reinterpret_cast<unsigned*>(&h1);
            *(uint2*)(g_M16 + ((size_t)v * DOUT + n) * DIN + (size_t)k4 * 4) = o;
        }
    }
}

// =================================================================
// Kernel 2: GEMM  out[srow[r]] = M16[level] @ x[srow[r]] + bias
//   A = fp32 x rows gathered directly (cp.async 256B rows), converted
//   to fp16 in registers at fragment load (LDS.64 + cvt).
//   B = fp16 g_M16 via ldmatrix. 8 warps of 32x64, 2 CTAs/SM.
// =================================================================
__global__ void __launch_bounds__(256, 2) padic_gemm(
    const float* __restrict__ x, const float* __restrict__ bias,
    float* __restrict__ out) {
    // ---- tile map ----
    int mt = blockIdx.x, ntile = blockIdx.y;
    int level = -1, tj = 0, acc = 0;
#pragma unroll
    for (int l = 0; l < NLEV; l++) {
        int c = g_counts[l];
        int tl = (c + BM - 1) >> 7;
        if (level < 0 && mt < acc + tl) { level = l; tj = mt - acc; }
        acc += tl;
    }
    if (level < 0) return;
    int base = g_offsets[level] + tj * BM;
    int cnt  = g_counts[level] - tj * BM;
    if (cnt > BM) cnt = BM;

    extern __shared__ char smem[];
    __shared__ int srow[BM];
    uint32_t sb = smem_u32(smem);
    int tid = threadIdx.x, lane = tid & 31, wid = tid >> 5;
    int wm = (wid & 3) * 32;
    int wn = (wid >> 2) * 64;

    // cache gathered row ids
    if (tid < BM) srow[tid] = g_rows[base + (tid < cnt ? tid : 0)];
    __syncthreads();

    // ---- producers ----
    // A: thread t -> row (t>>4)+16s (s=0..7), 16B unit u=t&15 of 256B chunk
    int uA = tid & 15, rA0 = tid >> 4;
    const char* pA[8];
#pragma unroll
    for (int s = 0; s < 8; s++)
        pA[s] = (const char*)(x + (size_t)srow[rA0 + 16 * s] * DIN) + uA * 16;
    uint32_t sA0 = (uint32_t)rA0 * 256u + (uint32_t)((uA ^ ((rA0 & 7) << 1)) << 4);
    // B: thread t -> row (t>>3)+32s (s=0..3), unit u=t&7 of 128B chunk
    int uB = tid & 7, rB0 = tid >> 3;
    const char* pB = (const char*)(g_M16 + ((size_t)level * DOUT
                     + (size_t)(ntile * BN + rB0)) * DIN) + uB * 16;
    uint32_t sB0 = (uint32_t)A_SZ + (uint32_t)rB0 * 128u
                 + (uint32_t)((uB ^ (rB0 & 7)) << 4);

    float accum[2][8][4];
#pragma unroll
    for (int mf = 0; mf < 2; mf++)
#pragma unroll
        for (int nf = 0; nf < 8; nf++)
#pragma unroll
            for (int q = 0; q < 4; q++) accum[mf][nf][q] = 0.f;

    // ---- prologue: stage 0 ----
    {
#pragma unroll
        for (int s = 0; s < 8; s++)
            CP16(sb + sA0 + s * 4096, pA[s]);
#pragma unroll
        for (int s = 0; s < 4; s++)
            CP16(sb + sB0 + s * 4096, pB + (size_t)s * 32768);
        CP_COMMIT();
    }

    // consumer lane constants
    int sub = lane >> 3, rr = lane & 7;
    int brow = wn + (sub >> 1) * 8 + rr;
    int bu   = sub & 1;
    int xorv = (lane >> 2) << 1;          // A swizzle xor for this lane's rows
    int inb  = (lane & 1) << 3;           // byte-in-unit
    int au0  = (lane & 3) >> 1;           // unit within k-group
    uint32_t abase0 = (uint32_t)(wm + (lane >> 2)) * 256u;

    // ---- mainloop ----
    for (int kb = 0; kb < NKB; kb++) {
        CP_WAIT0();
        __syncthreads();

        if (kb + 1 < NKB) {
            uint32_t st = sb + ((kb + 1) & 1) * STG_TOT;
#pragma unroll
            for (int s = 0; s < 8; s++)
                CP16(st + sA0 + s * 4096, pA[s] + (kb + 1) * 256);
#pragma unroll
            for (int s = 0; s < 4; s++)
                CP16(st + sB0 + s * 4096, pB + (kb + 1) * 128 + (size_t)s * 32768);
        }
        CP_COMMIT();

        uint32_t stg = (uint32_t)((kb & 1) * STG_TOT);
        const char* As = smem + stg;
        uint32_t Bb = sb + stg + A_SZ;

#pragma unroll
        for (int g = 0; g < 4; g++) {
            int u0 = 4 * g + au0;
            uint32_t col0 = (uint32_t)(((u0      ^ xorv) << 4) + inb);
            uint32_t col2 = (uint32_t)((((u0 + 2) ^ xorv) << 4) + inb);
            uint32_t afr[2][4];
            uint32_t bfr[8][2];
#pragma unroll
            for (int mf = 0; mf < 2; mf++) {
                uint32_t rb = abase0 + (uint32_t)mf * 4096u;
                afr[mf][0] = cvt2(*(const float2*)(As + rb + col0));
                afr[mf][1] = cvt2(*(const float2*)(As + rb + 2048 + col0));
                afr[mf][2] = cvt2(*(const float2*)(As + rb + col2));
                afr[mf][3] = cvt2(*(const float2*)(As + rb + 2048 + col2));
            }
#pragma unroll
            for (int bf = 0; bf < 4; bf++) {
                int rown = brow + bf * 16;
                LDSM4(bfr[bf * 2][0], bfr[bf * 2][1], bfr[bf * 2 + 1][0], bfr[bf * 2 + 1][1],
                      Bb + swzB(rown, g * 2 + bu));
            }
#pragma unroll
            for (int mf = 0; mf < 2; mf++)
#pragma unroll
                for (int nf = 0; nf < 8; nf++)
                    mma16(accum[mf][nf], afr[mf], bfr[nf]);
        }
    }

    // ---- epilogue ----
    int colbase = ntile * BN + wn;
    float2 bb[8];
#pragma unroll
    for (int nf = 0; nf < 8; nf++)
        bb[nf] = __ldg((const float2*)(bias + colbase + nf * 8 + (lane & 3) * 2));
#pragma unroll
    for (int mf = 0; mf < 2; mf++) {
        int row0 = wm + mf * 16 + (lane >> 2);
        int row1 = row0 + 8;
        float* o0 = out + (size_t)srow[row0] * DOUT;
        float* o1 = out + (size_t)srow[row1] * DOUT;
        bool v0 = row0 < cnt, v1 = row1 < cnt;
#pragma unroll
        for (int nf = 0; nf < 8; nf++) {
            int col = colbase + nf * 8 + (lane & 3) * 2;
            if (v0) {
                float2 w0;
                w0.x = accum[mf][nf][0] + bb[nf].x;
                w0.y = accum[mf][nf][1] + bb[nf].y;
                *(float2*)(o0 + col) = w0;
            }
            if (v1) {
                float2 w1;
                w1.x = accum[mf][nf][2] + bb[nf].x;
                w1.y = accum[mf][nf][3] + bb[nf].y;
                *(float2*)(o1 + col) = w1;
            }
        }
    }
}

// =================================================================
// kernel_launch
// =================================================================
extern "C" void kernel_launch(void* const* d_in, const int* in_sizes, int n_in,
                              void* d_out, int out_size) {
    const float* x     = (const float*)d_in[0];
    const void*  val   = d_in[1];
    const float* W     = (const float*)d_in[2];
    const float* gates = (const float*)d_in[3];
    const float* attn  = (const float*)d_in[4];
    const float* bias  = (const float*)d_in[5];
    float*       out   = (float*)d_out;

    cudaFuncSetAttribute(padic_gemm, cudaFuncAttributeMaxDynamicSharedMemorySize, SMEM_BYTES);

    k_prep<<<NHB + 128, 512>>>(val, W, gates, attn);
    padic_gemm<<<dim3(MAX_MT, NT), 256, SMEM_BYTES>>>(x, bias, out);
}

// round 13
// speedup vs baseline: 1.0735x; 1.0735x over previous
#include <cuda_runtime.h>
#include <cuda_fp16.h>
#include <cstdint>

// ---------------- problem constants ----------------
#define B_SZ   32768
#define DIN    512
#define DOUT   512
#define NLEV   10
#define NHB    64                  // histogram/scatter blocks (x512 thr)

// ---------------- GEMM tiling ----------------
#define BM     128
#define BN     128
#define BK     64                  // k per stage: A fp32 256B/row, B fp16 128B/row
#define NKB    (DIN / BK)          // 8 K-blocks
#define MAX_MT 266
#define NT     (DOUT / BN)         // 4 N-tiles
#define A_SZ   (BM * 256)          // 32768 B per stage (fp32)
#define B_SZ_S (BN * 128)          // 16384 B per stage (fp16)
#define STG_TOT (A_SZ + B_SZ_S)    // 49152 B
#define SMEM_BYTES (2 * STG_TOT)   // 98304

// ---------------- device scratch ----------------
__device__ int g_part[NHB][16];
__device__ int g_counts[NLEV];
__device__ int g_offsets[NLEV];
__device__ int g_rows[B_SZ];
// folded per-level matrices in fp16, [level][n][k]
__device__ __align__(16) __half g_M16[NLEV * DOUT * DIN];

// ---------------- PTX helpers ----------------
__device__ __forceinline__ uint32_t smem_u32(const void* p) {
    uint32_t a;
    asm("{ .reg .u64 t; cvta.to.shared.u64 t, %1; cvt.u32.u64 %0, t; }" : "=r"(a) : "l"(p));
    return a;
}
#define CP16(dst, src) \
    asm volatile("cp.async.cg.shared.global [%0], [%1], 16;" :: "r"(dst), "l"(src))
#define CP_COMMIT() asm volatile("cp.async.commit_group;" ::: "memory")
#define CP_WAIT0()  asm volatile("cp.async.wait_group 0;" ::: "memory")

#define LDSM4(r0, r1, r2, r3, addr) \
    asm volatile("ldmatrix.sync.aligned.m8n8.x4.shared.b16 {%0,%1,%2,%3}, [%4];" \
        : "=r"(r0), "=r"(r1), "=r"(r2), "=r"(r3) : "r"(addr))

__device__ __forceinline__ void mma16(float* d, const uint32_t* a, const uint32_t* b) {
    asm volatile(
        "mma.sync.aligned.m16n8k16.row.col.f32.f16.f16.f32 "
        "{%0,%1,%2,%3}, {%4,%5,%6,%7}, {%8,%9}, {%0,%1,%2,%3};"
        : "+f"(d[0]), "+f"(d[1]), "+f"(d[2]), "+f"(d[3])
        : "r"(a[0]), "r"(a[1]), "r"(a[2]), "r"(a[3]), "r"(b[0]), "r"(b[1]));
}

__device__ __forceinline__ uint32_t cvt2(float2 f) {
    __half2 h = __floats2half2_rn(f.x, f.y);
    return *reinterpret_cast<uint32_t*>(&h);
}

// B smem swizzle (128B rows, 8 x 16B units)
__device__ __forceinline__ uint32_t swzB(int row, int u) {
    return (uint32_t)row * 128u + (uint32_t)((u ^ (row & 7)) << 4);
}

// per-block int64-vs-int32 detection over first 2KB
__device__ __forceinline__ int detect_is64(const void* val, int tid) {
    int bad = 0;
    if (tid < 256) bad = (((const unsigned long long*)val)[tid] >= 10ULL);
    return __syncthreads_count(bad) == 0;
}
__device__ __forceinline__ int load_val(const void* val, int b, int is64) {
    int v = is64 ? (int)((const long long*)val)[b] : ((const int*)val)[b];
    return v < 0 ? 0 : (v > 9 ? 9 : v);
}

// =================================================================
// Kernel 1 (fused, independent halves):
//   blocks 0..63   : per-block histogram partials -> g_part
//   blocks 64..191 : fold M[v] = sum_l C[v,l]*W[l] (fp16 out)
// =================================================================
__global__ void k_prep(const void* __restrict__ val, const float* __restrict__ W,
                       const float* __restrict__ gates, const float* __restrict__ attn) {
    int tid = threadIdx.x, bid = blockIdx.x;
    if (bid < NHB) {
        __shared__ int sc[NLEV];
        int is64 = detect_is64(val, tid);          // includes a __syncthreads
        if (tid < NLEV) sc[tid] = 0;
        __syncthreads();
        atomicAdd(&sc[load_val(val, bid * 512 + tid, is64)], 1);
        __syncthreads();
        if (tid < NLEV) g_part[bid][tid] = sc[tid];
    } else {
        __shared__ float sC[NLEV][NLEV];
        if (tid < NLEV) {
            int v = tid;
            float m = -1e30f;
            for (int l = 0; l < NLEV; l++) m = fmaxf(m, attn[v * NLEV + l]);
            float e[NLEV]; float ssum = 0.f;
            for (int l = 0; l < NLEV; l++) { e[l] = expf(attn[v * NLEV + l] - m); ssum += e[l]; }
            float inv = 1.f / ssum;
            float gv = 1.f / (1.f + expf(-gates[v]));
            for (int l = 0; l < NLEV; l++) {
                float gl = 1.f / (1.f + expf(-gates[l]));
                sC[v][l] = 0.3f * e[l] * inv * gl + ((l == v) ? 0.7f * gv : 0.f);
            }
        }
        __syncthreads();

        int p  = (bid - NHB) * 512 + tid;         // 0 .. 65535
        int n  = p >> 7;                          // output feature 0..511
        int k4 = p & 127;                         // float4 index along K

        float4 w[NLEV];
#pragma unroll
        for (int l = 0; l < NLEV; l++)
            w[l] = __ldg((const float4*)(W + ((size_t)l * DOUT + n) * DIN) + k4);

#pragma unroll
        for (int v = 0; v < NLEV; v++) {
            float4 a = make_float4(0.f, 0.f, 0.f, 0.f);
#pragma unroll
            for (int l = 0; l < NLEV; l++) {
                float cc = sC[v][l];
                a.x += cc * w[l].x; a.y += cc * w[l].y;
                a.z += cc * w[l].z; a.w += cc * w[l].w;
            }
            __half2 h0 = __floats2half2_rn(a.x, a.y);
            __half2 h1 = __floats2half2_rn(a.z, a.w);
            uint2 o;
            o.x = *reinterpret_cast<unsigned*>(&h0);
            o.y = *reinterpret_cast<unsigned*>(&h1);
            *(uint2*)(g_M16 + ((size_t)v * DOUT + n) * DIN + (size_t)k4 * 4) = o;
        }
    }
}

// =================================================================
// Kernel 2: scan partials + scatter g_rows (scatter only, no gather)
// =================================================================
__global__ void k_scatter(const void* __restrict__ val) {
    __shared__ int scnt[NLEV], sprev[NLEV], sbase[NLEV], srank[NLEV];
    int tid = threadIdx.x, bid = blockIdx.x;
    int is64 = detect_is64(val, tid);

    if (tid < NLEV) {
        int tot = 0, before = 0;
        for (int b = 0; b < NHB; b++) {
            int p = g_part[b][tid];
            if (b < bid) before += p;
            tot += p;
        }
        scnt[tid] = tot; sprev[tid] = before; srank[tid] = 0;
    }
    __syncthreads();
    if (tid == 0) {
        int a = 0;
        for (int l = 0; l < NLEV; l++) {
            sbase[l] = a + sprev[l];
            if (bid == 0) { g_counts[l] = scnt[l]; g_offsets[l] = a; }
            a += scnt[l];
        }
    }
    __syncthreads();

    int b = bid * 512 + tid;
    int v = load_val(val, b, is64);
    int rank = atomicAdd(&srank[v], 1);
    g_rows[sbase[v] + rank] = b;
}

// =================================================================
// Kernel 3: GEMM  out[srow[r]] = M16[level] @ x[srow[r]] + bias
//   A = fp32 x rows gathered directly (cp.async 256B rows), converted
//   to fp16 in registers at fragment load (LDS.64 + cvt).
//   B = fp16 g_M16 via ldmatrix. 8 warps of 32x64, 2 CTAs/SM.
//   (At the legacy mma.sync issue floor: measured 64us == model.)
// =================================================================
__global__ void __launch_bounds__(256, 2) padic_gemm(
    const float* __restrict__ x, const float* __restrict__ bias,
    float* __restrict__ out) {
    // ---- tile map ----
    int mt = blockIdx.x, ntile = blockIdx.y;
    int level = -1, tj = 0, acc = 0;
#pragma unroll
    for (int l = 0; l < NLEV; l++) {
        int c = g_counts[l];
        int tl = (c + BM - 1) >> 7;
        if (level < 0 && mt < acc + tl) { level = l; tj = mt - acc; }
        acc += tl;
    }
    if (level < 0) return;
    int base = g_offsets[level] + tj * BM;
    int cnt  = g_counts[level] - tj * BM;
    if (cnt > BM) cnt = BM;

    extern __shared__ char smem[];
    __shared__ int srow[BM];
    uint32_t sb = smem_u32(smem);
    int tid = threadIdx.x, lane = tid & 31, wid = tid >> 5;
    int wm = (wid & 3) * 32;
    int wn = (wid >> 2) * 64;

    // cache gathered row ids
    if (tid < BM) srow[tid] = g_rows[base + (tid < cnt ? tid : 0)];
    __syncthreads();

    // ---- producers ----
    // A: thread t -> row (t>>4)+16s (s=0..7), 16B unit u=t&15 of 256B chunk
    int uA = tid & 15, rA0 = tid >> 4;
    const char* pA[8];
#pragma unroll
    for (int s = 0; s < 8; s++)
        pA[s] = (const char*)(x + (size_t)srow[rA0 + 16 * s] * DIN) + uA * 16;
    uint32_t sA0 = (uint32_t)rA0 * 256u + (uint32_t)((uA ^ ((rA0 & 7) << 1)) << 4);
    // B: thread t -> row (t>>3)+32s (s=0..3), unit u=t&7 of 128B chunk
    int uB = tid & 7, rB0 = tid >> 3;
    const char* pB = (const char*)(g_M16 + ((size_t)level * DOUT
                     + (size_t)(ntile * BN + rB0)) * DIN) + uB * 16;
    uint32_t sB0 = (uint32_t)A_SZ + (uint32_t)rB0 * 128u
                 + (uint32_t)((uB ^ (rB0 & 7)) << 4);

    float accum[2][8][4];
#pragma unroll
    for (int mf = 0; mf < 2; mf++)
#pragma unroll
        for (int nf = 0; nf < 8; nf++)
#pragma unroll
            for (int q = 0; q < 4; q++) accum[mf][nf][q] = 0.f;

    // ---- prologue: stage 0 ----
    {
#pragma unroll
        for (int s = 0; s < 8; s++)
            CP16(sb + sA0 + s * 4096, pA[s]);
#pragma unroll
        for (int s = 0; s < 4; s++)
            CP16(sb + sB0 + s * 4096, pB + (size_t)s * 32768);
        CP_COMMIT();
    }

    // consumer lane constants
    int sub = lane >> 3, rr = lane & 7;
    int brow = wn + (sub >> 1) * 8 + rr;
    int bu   = sub & 1;
    int xorv = (lane >> 2) << 1;          // A swizzle xor for this lane's rows
    int inb  = (lane & 1) << 3;           // byte-in-unit
    int au0  = (lane & 3) >> 1;           // unit within k-group
    uint32_t abase0 = (uint32_t)(wm + (lane >> 2)) * 256u;

    // ---- mainloop ----
    for (int kb = 0; kb < NKB; kb++) {
        CP_WAIT0();
        __syncthreads();

        if (kb + 1 < NKB) {
            uint32_t st = sb + ((kb + 1) & 1) * STG_TOT;
#pragma unroll
            for (int s = 0; s < 8; s++)
                CP16(st + sA0 + s * 4096, pA[s] + (kb + 1) * 256);
#pragma unroll
            for (int s = 0; s < 4; s++)
                CP16(st + sB0 + s * 4096, pB + (kb + 1) * 128 + (size_t)s * 32768);
        }
        CP_COMMIT();

        uint32_t stg = (uint32_t)((kb & 1) * STG_TOT);
        const char* As = smem + stg;
        uint32_t Bb = sb + stg + A_SZ;

#pragma unroll
        for (int g = 0; g < 4; g++) {
            int u0 = 4 * g + au0;
            uint32_t col0 = (uint32_t)(((u0      ^ xorv) << 4) + inb);
            uint32_t col2 = (uint32_t)((((u0 + 2) ^ xorv) << 4) + inb);
            uint32_t afr[2][4];
            uint32_t bfr[8][2];
#pragma unroll
            for (int mf = 0; mf < 2; mf++) {
                uint32_t rb = abase0 + (uint32_t)mf * 4096u;
                afr[mf][0] = cvt2(*(const float2*)(As + rb + col0));
                afr[mf][1] = cvt2(*(const float2*)(As + rb + 2048 + col0));
                afr[mf][2] = cvt2(*(const float2*)(As + rb + col2));
                afr[mf][3] = cvt2(*(const float2*)(As + rb + 2048 + col2));
            }
#pragma unroll
            for (int bf = 0; bf < 4; bf++) {
                int rown = brow + bf * 16;
                LDSM4(bfr[bf * 2][0], bfr[bf * 2][1], bfr[bf * 2 + 1][0], bfr[bf * 2 + 1][1],
                      Bb + swzB(rown, g * 2 + bu));
            }
#pragma unroll
            for (int mf = 0; mf < 2; mf++)
#pragma unroll
                for (int nf = 0; nf < 8; nf++)
                    mma16(accum[mf][nf], afr[mf], bfr[nf]);
        }
    }

    // ---- epilogue ----
    int colbase = ntile * BN + wn;
    float2 bb[8];
#pragma unroll
    for (int nf = 0; nf < 8; nf++)
        bb[nf] = __ldg((const float2*)(bias + colbase + nf * 8 + (lane & 3) * 2));
#pragma unroll
    for (int mf = 0; mf < 2; mf++) {
        int row0 = wm + mf * 16 + (lane >> 2);
        int row1 = row0 + 8;
        float* o0 = out + (size_t)srow[row0] * DOUT;
        float* o1 = out + (size_t)srow[row1] * DOUT;
        bool v0 = row0 < cnt, v1 = row1 < cnt;
#pragma unroll
        for (int nf = 0; nf < 8; nf++) {
            int col = colbase + nf * 8 + (lane & 3) * 2;
            if (v0) {
                float2 w0;
                w0.x = accum[mf][nf][0] + bb[nf].x;
                w0.y = accum[mf][nf][1] + bb[nf].y;
                *(float2*)(o0 + col) = w0;
            }
            if (v1) {
                float2 w1;
                w1.x = accum[mf][nf][2] + bb[nf].x;
                w1.y = accum[mf][nf][3] + bb[nf].y;
                *(float2*)(o1 + col) = w1;
            }
        }
    }
}

// =================================================================
// kernel_launch
// =================================================================
extern "C" void kernel_launch(void* const* d_in, const int* in_sizes, int n_in,
                              void* d_out, int out_size) {
    const float* x     = (const float*)d_in[0];
    const void*  val   = d_in[1];
    const float* W     = (const float*)d_in[2];
    const float* gates = (const float*)d_in[3];
    const float* attn  = (const float*)d_in[4];
    const float* bias  = (const float*)d_in[5];
    float*       out   = (float*)d_out;

    cudaFuncSetAttribute(padic_gemm, cudaFuncAttributeMaxDynamicSharedMemorySize, SMEM_BYTES);

    k_prep<<<NHB + 128, 512>>>(val, W, gates, attn);     // hist || fold
    k_scatter<<<NHB, 512>>>(val);                        // scan + scatter only
    padic_gemm<<<dim3(MAX_MT, NT), 256, SMEM_BYTES>>>(x, bias, out);
}